// round 16
// baseline (speedup 1.0000x reference)
#include <cuda_runtime.h>

#define N3 262144
#define N2 65536
#define N1 16384

typedef unsigned long long ull;

// ---------------- scratch (device globals; no allocations allowed) ----------
__device__ float g_x8   [N3 * 16];
__device__ float g_x7p  [N2 * 16];
__device__ float g_x7   [N2 * 32];
__device__ float g_x6p  [N1 * 32];
__device__ float g_x6   [N1 * 64];
__device__ float g_x7dec[N2 * 32];
__device__ float g_x8dec[N3 * 16];
__device__ int   g_pidx3[N3];
__device__ int   g_pidx2[N2];

// ---------------- packed f32x2 helpers ---------------------------------------
__device__ __forceinline__ ull pack2(float lo, float hi) {
    ull r;
    asm("mov.b64 %0, {%1, %2};" : "=l"(r) : "f"(lo), "f"(hi));
    return r;
}
__device__ __forceinline__ ull bcast2(float v) {
    ull r;
    asm("mov.b64 %0, {%1, %1};" : "=l"(r) : "f"(v));
    return r;
}
__device__ __forceinline__ void ffma2(ull& d, ull a, ull b) {
    asm("fma.rn.f32x2 %0, %1, %2, %0;" : "+l"(d) : "l"(a), "l"(b));
}
__device__ __forceinline__ float2 unpack2(ull v) {
    float2 r;
    asm("mov.b64 {%0, %1}, %2;" : "=f"(r.x), "=f"(r.y) : "l"(v));
    return r;
}

// ---------------- fused prep: pidx3, pidx2, zero x7p, zero x6p ---------------
__device__ __forceinline__ int lower_bound_shift(const int* __restrict__ keys,
                                                 int Np, int v) {
    int lo = 0, hi = Np;
    while (lo < hi) {
        int mid = (lo + hi) >> 1;
        if (keys[mid] < v) lo = mid + 1; else hi = mid;
    }
    return lo;
}

__global__ void prep_kernel(const int* __restrict__ keys3,
                            const int* __restrict__ keys2,
                            const int* __restrict__ keys1,
                            int* __restrict__ pidx3, int* __restrict__ pidx2,
                            float* __restrict__ x7p, float* __restrict__ x6p) {
    const int T0 = N3;
    const int T1 = T0 + N2;
    const int T2 = T1 + N2 * 16;
    const int T3 = T2 + N1 * 32;
    int i = blockIdx.x * blockDim.x + threadIdx.x;
    int stride = gridDim.x * blockDim.x;
    for (; i < T3; i += stride) {
        if (i < T0) {
            pidx3[i] = lower_bound_shift(keys2, N2, keys3[i] >> 2);
        } else if (i < T1) {
            int k = i - T0;
            pidx2[k] = lower_bound_shift(keys1, N1, keys2[k] >> 2);
        } else if (i < T2) {
            x7p[i - T1] = 0.0f;
        } else {
            x6p[i - T2] = 0.0f;
        }
    }
}

// segment-max pool. Post-ReLU values >= 0, so int-bit atomicMax == float max
// and 0-init matches the reference's (-inf -> 0) fill.
template <int C>
__global__ void pool_kernel(const float* __restrict__ child,
                            const int* __restrict__ pidx,
                            int Nc, int Np, float* __restrict__ parent) {
    int i = blockIdx.x * blockDim.x + threadIdx.x;
    if (i >= Nc * C) return;
    int node = i / C;
    int c = i - node * C;
    int p = pidx[node];
    if (p < Np) {
        float v = child[i];
        atomicMax(reinterpret_cast<int*>(&parent[(size_t)p * C + c]),
                  __float_as_int(v));
    }
}

// ======================= two-phase im2col GEMM conv ==========================
// Phase A: cooperative gather. 4 lanes per feature row, each LDG.128 touches
// only 8 distinct rows (vs 32 scattered) -> 4x fewer L1 wavefronts; every row
// fetched once per block. Stored rc-major: act[rc][node], stride TN+4 floats
// (16B-aligned, <=2-way STS conflicts).
// Phase B: smem GEMM. Thread owns NPB=4 nodes x PT output-pairs. Per rc:
// 1 broadcast LDS.128 (acts of 4 nodes, 1 wavefront/warp) + PT/2 coalesced
// weight LDS.128 (1 wavefront/warp) + 4*PT ffma2.
// K-chunked over neighbor groups of 3 to bound smem.
// INDIRECT fuses the unpool gather (row = clamp(pidx[idx])).
template <int CIN, int COUT, int TN, int PT, bool RELU, bool INDIRECT>
__global__ void __launch_bounds__(128)
conv_gemm(const float* __restrict__ feat, const int* __restrict__ neigh,
          const int* __restrict__ pidx, int Nfeat,
          const float* __restrict__ w, const float* __restrict__ b,
          float* __restrict__ out) {
    constexpr int BT = 128;
    constexpr int NPB = 4;
    constexpr int PAIRS = COUT / 2;
    constexpr int SUBS = PAIRS / PT;
    constexpr int JC = 3;               // neighbors per chunk
    constexpr int RCC = JC * CIN;       // rc entries per chunk
    constexpr int STR = TN + 4;         // act stride in floats (16B-aligned)
    constexpr int CIN9 = 9 * CIN;
    static_assert((TN / NPB) * SUBS == BT, "thread map");
    static_assert(CIN % 16 == 0, "phase A needs CIN%16==0");

    extern __shared__ __align__(16) char smem[];
    int* snidx = reinterpret_cast<int*>(smem);                   // TN*9 ints
    float* act = reinterpret_cast<float*>(smem + ((TN * 9 * 4 + 15) & ~15));
    ull* ws = reinterpret_cast<ull*>(
        reinterpret_cast<char*>(act) + RCC * STR * 4);           // RCC*PAIRS

    const int tid = threadIdx.x;
    const int node0 = blockIdx.x * TN;

    // stage neighbor ids (coalesced; INDIRECT adds scattered pidx lookups)
    for (int s = tid; s < TN * 9; s += BT) {
        int v = neigh[(size_t)node0 * 9 + s];
        if (INDIRECT) {
            if (v >= 0) {
                int p = pidx[v];
                v = p < Nfeat ? p : Nfeat - 1;
            }
        }
        snidx[s] = v;
    }

    // phase-B thread mapping
    const int sub = tid % SUBS;
    const int ng = tid / SUBS;
    const int n0 = ng * NPB;

    ull acc[NPB][PT];
#pragma unroll
    for (int p = 0; p < PT; p++) {
        ull bv = pack2(b[2 * (sub * PT + p)], b[2 * (sub * PT + p) + 1]);
#pragma unroll
        for (int n = 0; n < NPB; n++) acc[n][p] = bv;
    }
    __syncthreads();

    constexpr int M = CIN / 16;          // float4 chunks per lane per row
    constexpr int ROWS_IT = BT / 4;      // 32 rows per gather iteration
    constexpr int CROWS = TN * JC;       // rows per chunk
    const int lane4 = tid & 3;
    const int rbase = tid >> 2;

    for (int c = 0; c < 9 / JC; c++) {
        // ---- phase A: weights for this chunk ----
        for (int s = tid; s < RCC * PAIRS; s += BT) {
            int rc = s / PAIRS;
            int o2 = s - rc * PAIRS;
            int rcg = c * RCC + rc;
            ws[s] = pack2(w[(size_t)(2 * o2) * CIN9 + rcg],
                          w[(size_t)(2 * o2 + 1) * CIN9 + rcg]);
        }
        // ---- phase A: im2col gather for this chunk ----
#pragma unroll
        for (int it = 0; it < CROWS / ROWS_IT; it++) {
            int r = it * ROWS_IT + rbase;
            int nd = r / JC;
            int jl = r - nd * JC;
            int id = snidx[nd * 9 + c * JC + jl];
#pragma unroll
            for (int m = 0; m < M; m++) {
                int c4 = 4 * (lane4 + 4 * m);
                float4 f = (id >= 0)
                    ? *reinterpret_cast<const float4*>(
                          &feat[(size_t)id * CIN + c4])
                    : make_float4(0.f, 0.f, 0.f, 0.f);
                int rc = jl * CIN + c4;
                act[(rc + 0) * STR + nd] = f.x;
                act[(rc + 1) * STR + nd] = f.y;
                act[(rc + 2) * STR + nd] = f.z;
                act[(rc + 3) * STR + nd] = f.w;
            }
        }
        __syncthreads();
        // ---- phase B: GEMM from smem ----
#pragma unroll 3
        for (int rc = 0; rc < RCC; rc++) {
            float4 a = *reinterpret_cast<const float4*>(&act[rc * STR + n0]);
            const ull* wrow = ws + rc * PAIRS + sub * PT;
#pragma unroll
            for (int p2 = 0; p2 < PT; p2 += 2) {
                ulonglong2 wl =
                    *reinterpret_cast<const ulonglong2*>(wrow + p2);
                ffma2(acc[0][p2], bcast2(a.x), wl.x);
                ffma2(acc[0][p2 + 1], bcast2(a.x), wl.y);
                ffma2(acc[1][p2], bcast2(a.y), wl.x);
                ffma2(acc[1][p2 + 1], bcast2(a.y), wl.y);
                ffma2(acc[2][p2], bcast2(a.z), wl.x);
                ffma2(acc[2][p2 + 1], bcast2(a.z), wl.y);
                ffma2(acc[3][p2], bcast2(a.w), wl.x);
                ffma2(acc[3][p2 + 1], bcast2(a.w), wl.y);
            }
        }
        __syncthreads();
    }

    // ---- writeout: node n0+n, outputs [2*sub*PT, 2*sub*PT + 2*PT) ----
    const int oc0 = 2 * sub * PT;
#pragma unroll
    for (int n = 0; n < NPB; n++) {
        float* orow = out + (size_t)(node0 + n0 + n) * COUT + oc0;
#pragma unroll
        for (int p2 = 0; p2 < PT; p2 += 2) {
            float2 q0 = unpack2(acc[n][p2]);
            float2 q1 = unpack2(acc[n][p2 + 1]);
            float4 v;
            v.x = RELU ? fmaxf(q0.x, 0.f) : q0.x;
            v.y = RELU ? fmaxf(q0.y, 0.f) : q0.y;
            v.z = RELU ? fmaxf(q1.x, 0.f) : q1.x;
            v.w = RELU ? fmaxf(q1.y, 0.f) : q1.y;
            *reinterpret_cast<float4*>(orow + 2 * p2) = v;
        }
    }
}

// ---------------- small layers (enc1 CIN=1, head COUT=1) ---------------------
template <int CIN, int COB, int NPN, bool RELU>
__global__ void __launch_bounds__(256)
conv_small(const float* __restrict__ feat, const int* __restrict__ neigh,
           int ostride, const float* __restrict__ w,
           const float* __restrict__ b, float* __restrict__ out) {
    extern __shared__ __align__(16) char smem_raw[];
    const int tid = threadIdx.x;
    const int cin9 = 9 * CIN;

    if constexpr (COB == 1) {
        float* ws = reinterpret_cast<float*>(smem_raw);
        for (int s = tid; s < cin9; s += 256) ws[s] = w[s];
        __syncthreads();

        int node[NPN];
        int idx[NPN][9];
#pragma unroll
        for (int t = 0; t < NPN; t++) {
            node[t] = blockIdx.x * (256 * NPN) + t * 256 + tid;
#pragma unroll
            for (int j = 0; j < 9; j++)
                idx[t][j] = neigh[(size_t)node[t] * 9 + j];
        }
        float acc[NPN];
#pragma unroll
        for (int t = 0; t < NPN; t++) acc[t] = b[0];
        for (int j = 0; j < 9; j++) {
            float4 f[NPN][CIN / 4];
#pragma unroll
            for (int t = 0; t < NPN; t++)
#pragma unroll
                for (int k = 0; k < CIN / 4; k++)
                    f[t][k] = (idx[t][j] >= 0)
                        ? *reinterpret_cast<const float4*>(
                              &feat[(size_t)idx[t][j] * CIN + 4 * k])
                        : make_float4(0.f, 0.f, 0.f, 0.f);
#pragma unroll
            for (int k = 0; k < CIN / 4; k++) {
                float4 wv = *reinterpret_cast<const float4*>(
                    &ws[j * CIN + 4 * k]);
#pragma unroll
                for (int t = 0; t < NPN; t++)
                    acc[t] += f[t][k].x * wv.x + f[t][k].y * wv.y +
                              f[t][k].z * wv.z + f[t][k].w * wv.w;
            }
        }
#pragma unroll
        for (int t = 0; t < NPN; t++)
            out[(size_t)node[t] * ostride] = RELU ? fmaxf(acc[t], 0.f) : acc[t];
    } else {
        static_assert(COB == 1 || CIN == 1, "small path");
        constexpr int PAIRS = COB / 2;
        ull* ws = reinterpret_cast<ull*>(smem_raw);
        for (int s = tid; s < cin9 * PAIRS; s += 256) {
            int rc = s / PAIRS;
            int o2 = s - rc * PAIRS;
            ws[s] = pack2(w[(size_t)(2 * o2) * cin9 + rc],
                          w[(size_t)(2 * o2 + 1) * cin9 + rc]);
        }
        __syncthreads();

        int node[NPN];
        int idx[NPN][9];
#pragma unroll
        for (int t = 0; t < NPN; t++) {
            node[t] = blockIdx.x * (256 * NPN) + t * 256 + tid;
#pragma unroll
            for (int j = 0; j < 9; j++)
                idx[t][j] = neigh[(size_t)node[t] * 9 + j];
        }
        ull acc2[NPN][PAIRS];
#pragma unroll
        for (int o2 = 0; o2 < PAIRS; o2++) {
            ull bv = pack2(b[2 * o2], b[2 * o2 + 1]);
#pragma unroll
            for (int t = 0; t < NPN; t++) acc2[t][o2] = bv;
        }
        float fv[NPN][9];
#pragma unroll
        for (int t = 0; t < NPN; t++)
#pragma unroll
            for (int j = 0; j < 9; j++)
                fv[t][j] = (idx[t][j] >= 0) ? __ldg(&feat[idx[t][j]]) : 0.f;
#pragma unroll
        for (int j = 0; j < 9; j++) {
            ull ff[NPN];
#pragma unroll
            for (int t = 0; t < NPN; t++) ff[t] = bcast2(fv[t][j]);
            const ull* wrow = ws + j * PAIRS;
#pragma unroll
            for (int og = 0; og < PAIRS; og += 2) {
                ulonglong2 wl = *reinterpret_cast<const ulonglong2*>(wrow + og);
#pragma unroll
                for (int t = 0; t < NPN; t++) {
                    ffma2(acc2[t][og], ff[t], wl.x);
                    ffma2(acc2[t][og + 1], ff[t], wl.y);
                }
            }
        }
#pragma unroll
        for (int t = 0; t < NPN; t++) {
            float* orow = out + (size_t)node[t] * ostride;
#pragma unroll
            for (int o = 0; o < COB; o += 4) {
                float2 p0 = unpack2(acc2[t][o / 2]);
                float2 p1 = unpack2(acc2[t][o / 2 + 1]);
                float4 v;
                v.x = RELU ? fmaxf(p0.x, 0.f) : p0.x;
                v.y = RELU ? fmaxf(p0.y, 0.f) : p0.y;
                v.z = RELU ? fmaxf(p1.x, 0.f) : p1.x;
                v.w = RELU ? fmaxf(p1.y, 0.f) : p1.y;
                *reinterpret_cast<float4*>(orow + o) = v;
            }
        }
    }
}

// ---------------- launch ------------------------------------------------------
static inline int cdiv(int a, int b) { return (a + b - 1) / b; }

// smem sizes: align16(TN*9*4) + (3*CIN)*(TN+4)*4 + (3*CIN)*(COUT/2)*8
#define SMEM_GEMM(CIN, COUT, TN) \
    ((((TN) * 36 + 15) & ~15) + (3 * (CIN)) * ((TN) + 4) * 4 + \
     (3 * (CIN)) * ((COUT) / 2) * 8)

extern "C" void kernel_launch(void* const* d_in, const int* in_sizes, int n_in,
                              void* d_out, int out_size) {
    const float* features = (const float*)d_in[0];
    const int* keys3   = (const int*)d_in[1];
    const int* keys2   = (const int*)d_in[2];
    const int* keys1   = (const int*)d_in[3];
    const int* neighs3 = (const int*)d_in[4];
    const int* neighs2 = (const int*)d_in[5];
    const int* neighs1 = (const int*)d_in[6];
    const float* w_enc1 = (const float*)d_in[7];
    const float* b_enc1 = (const float*)d_in[8];
    const float* w_enc2 = (const float*)d_in[9];
    const float* b_enc2 = (const float*)d_in[10];
    const float* w_enc3 = (const float*)d_in[11];
    const float* b_enc3 = (const float*)d_in[12];
    const float* w_dec1 = (const float*)d_in[13];
    const float* b_dec1 = (const float*)d_in[14];
    const float* w_dec2 = (const float*)d_in[15];
    const float* b_dec2 = (const float*)d_in[16];
    const float* w_head = (const float*)d_in[17];
    const float* b_head = (const float*)d_in[18];
    float* out = (float*)d_out;

    float *x8, *x7p, *x7, *x6p, *x6, *x7dec, *x8dec;
    int *pidx3, *pidx2;
    cudaGetSymbolAddress((void**)&x8, g_x8);
    cudaGetSymbolAddress((void**)&x7p, g_x7p);
    cudaGetSymbolAddress((void**)&x7, g_x7);
    cudaGetSymbolAddress((void**)&x6p, g_x6p);
    cudaGetSymbolAddress((void**)&x6, g_x6);
    cudaGetSymbolAddress((void**)&x7dec, g_x7dec);
    cudaGetSymbolAddress((void**)&x8dec, g_x8dec);
    cudaGetSymbolAddress((void**)&pidx3, g_pidx3);
    cudaGetSymbolAddress((void**)&pidx2, g_pidx2);

    constexpr int SM_ENC2 = SMEM_GEMM(16, 32, 64);   // ~21.5KB
    constexpr int SM_ENC3 = SMEM_GEMM(32, 64, 64);   // ~53KB
    constexpr int SM_DEC1 = SMEM_GEMM(64, 32, 64);   // ~79KB
    constexpr int SM_DEC2 = SMEM_GEMM(32, 16, 128);  // ~61.5KB

    cudaFuncSetAttribute((const void*)conv_gemm<32, 64, 64, 4, true, false>,
                         cudaFuncAttributeMaxDynamicSharedMemorySize, SM_ENC3);
    cudaFuncSetAttribute((const void*)conv_gemm<64, 32, 64, 2, true, true>,
                         cudaFuncAttributeMaxDynamicSharedMemorySize, SM_DEC1);
    cudaFuncSetAttribute((const void*)conv_gemm<32, 16, 128, 2, true, true>,
                         cudaFuncAttributeMaxDynamicSharedMemorySize, SM_DEC2);

    // 0: fused prep (pidx3, pidx2, zero pool accumulators)
    prep_kernel<<<2048, 256>>>(keys3, keys2, keys1, pidx3, pidx2, x7p, x6p);

    // 1: enc1 [N3,1]->[N3,16]
    conv_small<1, 16, 2, true><<<512, 256, 576>>>(
        features, neighs3, 16, w_enc1, b_enc1, x8);
    // 2: pool 3->2
    pool_kernel<16><<<cdiv(N3 * 16, 256), 256>>>(x8, pidx3, N3, N2, x7p);
    // 3: enc2 [N2,16]->[N2,32]  TN=64 PT=2 SUBS=8  (1024 CTAs)
    conv_gemm<16, 32, 64, 2, true, false><<<N2 / 64, 128, SM_ENC2>>>(
        x7p, neighs2, nullptr, N2, w_enc2, b_enc2, x7);
    // 4: pool 2->1
    pool_kernel<32><<<cdiv(N2 * 32, 256), 256>>>(x7, pidx2, N2, N1, x6p);
    // 5: enc3 [N1,32]->[N1,64]  TN=64 PT=4 SUBS=8  (256 CTAs)
    conv_gemm<32, 64, 64, 4, true, false><<<N1 / 64, 128, SM_ENC3>>>(
        x6p, neighs1, nullptr, N1, w_enc3, b_enc3, x6);
    // 6: dec1 (unpool 1->2 fused) [N2,9*64]->[N2,32]  TN=64 PT=2  (1024 CTAs)
    conv_gemm<64, 32, 64, 2, true, true><<<N2 / 64, 128, SM_DEC1>>>(
        x6, neighs2, pidx2, N1, w_dec1, b_dec1, x7dec);
    // 7: dec2 (unpool 2->3 fused) [N3,9*32]->[N3,16]  TN=128 PT=2 (2048 CTAs)
    conv_gemm<32, 16, 128, 2, true, true><<<N3 / 128, 128, SM_DEC2>>>(
        x7dec, neighs3, pidx3, N2, w_dec2, b_dec2, x8dec);
    // 8: head [N3,16]->[N3,1], no relu
    conv_small<16, 1, 2, false><<<512, 256, 576>>>(
        x8dec, neighs3, 1, w_head, b_head, out);
}